// round 1
// baseline (speedup 1.0000x reference)
#include <cuda_runtime.h>
#include <cuda_bf16.h>

// Problem constants (capacities; runtime sizes derived from in_sizes)
#define D 128
#define MAXN 50176          // 196 * 256, >= 50000
#define MAXE 800000
#define SCAN_NB 196         // ceil(50000/256)

// ---------------- scratch (device globals; no allocation allowed) -----------
__device__ float g_Ah[MAXN * D];
__device__ float g_Bh[MAXN * D];
__device__ float g_Dh[MAXN * D];
__device__ float g_Eh[MAXN * D];
__device__ int   g_deg[MAXN];
__device__ int   g_off[MAXN + 1];
__device__ int   g_cur[MAXN];
__device__ int   g_csrc[MAXE];
__device__ int   g_bsums[256];

// ---------------- CSR build -------------------------------------------------
__global__ void k_zero_deg(int N) {
    int i = blockIdx.x * blockDim.x + threadIdx.x;
    if (i < N) g_deg[i] = 0;
}

__global__ void k_hist(const int* __restrict__ dst, int E) {
    int i = blockIdx.x * blockDim.x + threadIdx.x;
    if (i < E) atomicAdd(&g_deg[dst[i]], 1);
}

// per-block exclusive scan of 256 elements; block total to g_bsums
__global__ void k_scan1(int N) {
    __shared__ int s[256];
    int tid = threadIdx.x;
    int i = blockIdx.x * 256 + tid;
    int v = (i < N) ? g_deg[i] : 0;
    s[tid] = v;
    __syncthreads();
#pragma unroll
    for (int off = 1; off < 256; off <<= 1) {
        int t = (tid >= off) ? s[tid - off] : 0;
        __syncthreads();
        s[tid] += t;
        __syncthreads();
    }
    if (i < N) g_off[i] = s[tid] - v;    // exclusive within block
    if (tid == 255) g_bsums[blockIdx.x] = s[255];
}

__global__ void k_scan2(int nb, int N) {
    // single thread: scan block sums (tiny: <=196 values)
    if (threadIdx.x == 0 && blockIdx.x == 0) {
        int run = 0;
        for (int b = 0; b < nb; b++) {
            int t = g_bsums[b];
            g_bsums[b] = run;
            run += t;
        }
        g_off[N] = run;
    }
}

__global__ void k_scan3(int N) {
    int i = blockIdx.x * blockDim.x + threadIdx.x;
    if (i < N) {
        int v = g_off[i] + g_bsums[i >> 8];
        g_off[i] = v;
        g_cur[i] = v;
    }
}

__global__ void k_scatter(const int* __restrict__ src, const int* __restrict__ dst, int E) {
    int i = blockIdx.x * blockDim.x + threadIdx.x;
    if (i < E) {
        int d = dst[i];
        int p = atomicAdd(&g_cur[d], 1);
        g_csrc[p] = src[i];
    }
}

// ---------------- fused 4-way GEMM: out = (h*norm) @ W + b ------------------
// BM=64 rows, BN=128 cols (full), K=128 (full). 256 threads, 4x8 micro-tile.
__global__ void k_gemm4(const float* __restrict__ h, const float* __restrict__ norm,
                        const float* __restrict__ WA, const float* __restrict__ bA,
                        const float* __restrict__ WB, const float* __restrict__ bB,
                        const float* __restrict__ WD, const float* __restrict__ bD,
                        const float* __restrict__ WE, const float* __restrict__ bE,
                        int N) {
    extern __shared__ float sm[];
    float* As = sm;            // [128][64] transposed: As[k*64 + m]
    float* Ws = sm + 64 * 128; // [128][128]: Ws[k*128 + n]

    const float* W;
    const float* bias;
    float* outp;
    switch (blockIdx.y) {
        case 0:  W = WA; bias = bA; outp = g_Ah; break;
        case 1:  W = WB; bias = bB; outp = g_Bh; break;
        case 2:  W = WD; bias = bD; outp = g_Dh; break;
        default: W = WE; bias = bE; outp = g_Eh; break;
    }

    int tid = threadIdx.x;
    int rowbase = blockIdx.x * 64;

    // Load A tile (64x128), multiply by norm, store transposed.
    // 2048 float4 total, 8 per thread.
#pragma unroll
    for (int it = 0; it < 8; it++) {
        int idx = tid + it * 256;       // 0..2047
        int row = idx >> 5;             // 32 float4 per row
        int kq  = (idx & 31) << 2;
        int gr  = rowbase + row;
        float4 v = make_float4(0.f, 0.f, 0.f, 0.f);
        float nm = 0.f;
        if (gr < N) {
            v = *(const float4*)&h[gr * D + kq];
            nm = norm[gr];
        }
        As[(kq + 0) * 64 + row] = v.x * nm;
        As[(kq + 1) * 64 + row] = v.y * nm;
        As[(kq + 2) * 64 + row] = v.z * nm;
        As[(kq + 3) * 64 + row] = v.w * nm;
    }
    // Load W (128x128) straight copy: 4096 float4, 16 per thread.
#pragma unroll
    for (int it = 0; it < 16; it++) {
        int idx = tid + it * 256;
        ((float4*)Ws)[idx] = ((const float4*)W)[idx];
    }
    __syncthreads();

    int tx = tid & 15;  // m group (4 rows)
    int ty = tid >> 4;  // n group (8 cols)

    float acc[4][8];
#pragma unroll
    for (int i = 0; i < 4; i++)
#pragma unroll
        for (int j = 0; j < 8; j++) acc[i][j] = 0.f;

#pragma unroll 4
    for (int k = 0; k < 128; k++) {
        float4 a  = *(float4*)&As[k * 64 + tx * 4];
        float4 b0 = *(float4*)&Ws[k * 128 + ty * 8];
        float4 b1 = *(float4*)&Ws[k * 128 + ty * 8 + 4];
        float av[4] = {a.x, a.y, a.z, a.w};
        float bv[8] = {b0.x, b0.y, b0.z, b0.w, b1.x, b1.y, b1.z, b1.w};
#pragma unroll
        for (int i = 0; i < 4; i++)
#pragma unroll
            for (int j = 0; j < 8; j++)
                acc[i][j] = fmaf(av[i], bv[j], acc[i][j]);
    }

    float4 bb0 = *(const float4*)&bias[ty * 8];
    float4 bb1 = *(const float4*)&bias[ty * 8 + 4];
    float bvv[8] = {bb0.x, bb0.y, bb0.z, bb0.w, bb1.x, bb1.y, bb1.z, bb1.w};

#pragma unroll
    for (int i = 0; i < 4; i++) {
        int gr = rowbase + tx * 4 + i;
        if (gr < N) {
            float4 o0, o1;
            o0.x = acc[i][0] + bvv[0]; o0.y = acc[i][1] + bvv[1];
            o0.z = acc[i][2] + bvv[2]; o0.w = acc[i][3] + bvv[3];
            o1.x = acc[i][4] + bvv[4]; o1.y = acc[i][5] + bvv[5];
            o1.z = acc[i][6] + bvv[6]; o1.w = acc[i][7] + bvv[7];
            *(float4*)&outp[gr * D + ty * 8]     = o0;
            *(float4*)&outp[gr * D + ty * 8 + 4] = o1;
        }
    }
}

// ---------------- gather: per-node aggregation ------------------------------
__device__ __forceinline__ float fast_sigmoid(float x) {
    float t;
    asm("tanh.approx.f32 %0, %1;" : "=f"(t) : "f"(x * 0.5f));
    return fmaf(t, 0.5f, 0.5f);
}

__global__ void k_gather(const float* __restrict__ norm, float* __restrict__ out, int N) {
    int v = blockIdx.x;
    int d = threadIdx.x;
    float Ehd = g_Eh[v * D + d];
    int beg = g_off[v];
    int end = g_off[v + 1];
    float num = 0.f, den = 0.f;
    for (int i = beg; i < end; i++) {
        int s = g_csrc[i];
        float Dv = g_Dh[s * D + d];
        float Bv = g_Bh[s * D + d];
        float sg = fast_sigmoid(Dv + Ehd);
        num = fmaf(sg, Bv, num);
        den += sg;
    }
    float nm = norm[v];
    float ho = (g_Ah[v * D + d] + __fdividef(num, den + 1e-6f)) * nm;
    out[v * D + d] = ho;
}

// ---------------- e passthrough copy ----------------------------------------
__global__ void k_copy4(const float4* __restrict__ s, float4* __restrict__ dt, int n4) {
    int i = blockIdx.x * blockDim.x + threadIdx.x;
    if (i < n4) dt[i] = s[i];
}

// ---------------- launch -----------------------------------------------------
extern "C" void kernel_launch(void* const* d_in, const int* in_sizes, int n_in,
                              void* d_out, int out_size) {
    const float* h    = (const float*)d_in[0];
    const float* e    = (const float*)d_in[1];
    const float* norm = (const float*)d_in[2];
    const int*   src  = (const int*)d_in[3];
    const int*   dst  = (const int*)d_in[4];
    const float* WA = (const float*)d_in[5];
    const float* bA = (const float*)d_in[6];
    const float* WB = (const float*)d_in[7];
    const float* bB = (const float*)d_in[8];
    const float* WD = (const float*)d_in[9];
    const float* bD = (const float*)d_in[10];
    const float* WE = (const float*)d_in[11];
    const float* bE = (const float*)d_in[12];

    int N = in_sizes[0] / D;
    int E = in_sizes[1] / D;
    float* out = (float*)d_out;

    // CSR build
    int tb = 256;
    int gN = (N + tb - 1) / tb;
    int gE = (E + tb - 1) / tb;
    k_zero_deg<<<gN, tb>>>(N);
    k_hist<<<gE, tb>>>(dst, E);
    int nb = (N + 255) / 256;
    k_scan1<<<nb, 256>>>(N);
    k_scan2<<<1, 32>>>(nb, N);
    k_scan3<<<gN, tb>>>(N);
    k_scatter<<<gE, tb>>>(src, dst, E);

    // 4-way GEMM
    size_t smem = (64 * 128 + 128 * 128) * sizeof(float); // 96 KB
    cudaFuncSetAttribute(k_gemm4, cudaFuncAttributeMaxDynamicSharedMemorySize, (int)smem);
    dim3 ggrid((N + 63) / 64, 4);
    k_gemm4<<<ggrid, 256, smem>>>(h, norm, WA, bA, WB, bB, WD, bD, WE, bE, N);

    // gather + output
    k_gather<<<N, D>>>(norm, out, N);

    // e passthrough tail
    int tail = out_size - N * D;
    if (tail > 0) {
        int n4 = tail / 4;
        k_copy4<<<(n4 + 255) / 256, 256>>>((const float4*)e, (float4*)(out + (size_t)N * D), n4);
    }
}

// round 2
// speedup vs baseline: 1.4546x; 1.4546x over previous
#include <cuda_runtime.h>
#include <cuda_bf16.h>
#include <cstdint>

#define D 128
#define MAXN 50176
#define MAXE 800000

// ---------------- scratch ----------------------------------------------------
__device__ float g_Ah[MAXN * D];
__device__ float g_Bh[MAXN * D];
__device__ float g_Dh[MAXN * D];
__device__ float g_Eh[MAXN * D];
__device__ int   g_deg[MAXN];
__device__ int   g_off[MAXN + 1];
__device__ int   g_cur[MAXN];
__device__ int   g_csrc[MAXE];
__device__ int   g_bsums[256];

// ---------------- CSR build --------------------------------------------------
__global__ void k_zero_deg(int N) {
    int i = blockIdx.x * blockDim.x + threadIdx.x;
    if (i < N) g_deg[i] = 0;
}

__global__ void k_hist(const int* __restrict__ dst, int E) {
    int i = blockIdx.x * blockDim.x + threadIdx.x;
    if (i < E) atomicAdd(&g_deg[dst[i]], 1);
}

__global__ void k_scan1(int N) {
    __shared__ int s[256];
    int tid = threadIdx.x;
    int i = blockIdx.x * 256 + tid;
    int v = (i < N) ? g_deg[i] : 0;
    s[tid] = v;
    __syncthreads();
#pragma unroll
    for (int off = 1; off < 256; off <<= 1) {
        int t = (tid >= off) ? s[tid - off] : 0;
        __syncthreads();
        s[tid] += t;
        __syncthreads();
    }
    if (i < N) g_off[i] = s[tid] - v;
    if (tid == 255) g_bsums[blockIdx.x] = s[255];
}

// parallel scan of block sums (nb <= 256), single 256-thread block
__global__ void k_scan2(int nb, int N) {
    __shared__ int s[256];
    int tid = threadIdx.x;
    int v = (tid < nb) ? g_bsums[tid] : 0;
    s[tid] = v;
    __syncthreads();
#pragma unroll
    for (int off = 1; off < 256; off <<= 1) {
        int t = (tid >= off) ? s[tid - off] : 0;
        __syncthreads();
        s[tid] += t;
        __syncthreads();
    }
    if (tid < nb) g_bsums[tid] = s[tid] - v;   // exclusive
    if (tid == 255) g_off[N] = s[255];
}

__global__ void k_scan3(int N) {
    int i = blockIdx.x * blockDim.x + threadIdx.x;
    if (i < N) {
        int v = g_off[i] + g_bsums[i >> 8];
        g_off[i] = v;
        g_cur[i] = v;
    }
}

__global__ void k_scatter(const int* __restrict__ src, const int* __restrict__ dst, int E) {
    int i = blockIdx.x * blockDim.x + threadIdx.x;
    if (i < E) {
        int d = dst[i];
        int p = atomicAdd(&g_cur[d], 1);
        g_csrc[p] = src[i];
    }
}

// ---------------- tf32 tensor-core 4-way GEMM + interleaved e-copy ----------
// out = (h*norm) @ W + b for W in {WA,WB,WD,WE}. Tile 128x128, K=128 full.
// 256 threads = 8 warps; warp tile 32x64 via 2x8 mma.m16n8k8.tf32 tiles.
#define AS_STRIDE 132
#define WS_STRIDE 136
#define COPY_CHUNK 2048   // float4 per copy block

__device__ __forceinline__ float to_tf32(float x) {
    float r;
    asm("cvt.rna.tf32.f32 %0, %1;" : "=f"(r) : "f"(x));
    return r;
}

__device__ __forceinline__ void mma_tf32(float acc[4], const float a[4], const float b[2]) {
    asm volatile(
        "mma.sync.aligned.m16n8k8.row.col.f32.tf32.tf32.f32 "
        "{%0,%1,%2,%3}, {%4,%5,%6,%7}, {%8,%9}, {%0,%1,%2,%3};\n"
        : "+f"(acc[0]), "+f"(acc[1]), "+f"(acc[2]), "+f"(acc[3])
        : "r"(__float_as_uint(a[0])), "r"(__float_as_uint(a[1])),
          "r"(__float_as_uint(a[2])), "r"(__float_as_uint(a[3])),
          "r"(__float_as_uint(b[0])), "r"(__float_as_uint(b[1])));
}

__global__ __launch_bounds__(256, 1)
void k_gemm4_tf32(const float* __restrict__ h, const float* __restrict__ norm,
                  const float* __restrict__ WA, const float* __restrict__ bA,
                  const float* __restrict__ WB, const float* __restrict__ bB,
                  const float* __restrict__ WD, const float* __restrict__ bD,
                  const float* __restrict__ WE, const float* __restrict__ bE,
                  int N, int MT, int T1, int NC1,
                  const float4* __restrict__ esrc, float4* __restrict__ edst,
                  long n4total) {
    long b = blockIdx.x;
    long cb  = (b * NC1) / T1;
    long cb1 = ((b + 1) * NC1) / T1;
    int tid = threadIdx.x;

    if (cb1 > cb) {
        // ---- e-copy block ----
        long base = cb * COPY_CHUNK;
#pragma unroll
        for (int it = 0; it < COPY_CHUNK / 256; it++) {
            long idx = base + tid + it * 256;
            if (idx < n4total) __stcs(&edst[idx], __ldcs(&esrc[idx]));
        }
        return;
    }
    int gidx = (int)(b - cb);
    int mtile = gidx % MT;
    int which = gidx / MT;

    extern __shared__ float sm[];
    float* As = sm;                       // [128][AS_STRIDE]
    float* Ws = sm + 128 * AS_STRIDE;     // [128][WS_STRIDE]

    const float* W; const float* bias; float* outp;
    switch (which) {
        case 0:  W = WA; bias = bA; outp = g_Ah; break;
        case 1:  W = WB; bias = bB; outp = g_Bh; break;
        case 2:  W = WD; bias = bD; outp = g_Dh; break;
        default: W = WE; bias = bE; outp = g_Eh; break;
    }

    int rowbase = mtile * 128;

    // Load A tile (128x128), multiply by norm, cvt to tf32. 4096 float4, 16/thread.
#pragma unroll
    for (int it = 0; it < 16; it++) {
        int idx = tid + it * 256;
        int row = idx >> 5;
        int c4  = (idx & 31) << 2;
        int gr  = rowbase + row;
        float4 v = make_float4(0.f, 0.f, 0.f, 0.f);
        float nm = 0.f;
        if (gr < N) {
            v = *(const float4*)&h[gr * D + c4];
            nm = norm[gr];
        }
        float* p = &As[row * AS_STRIDE + c4];
        p[0] = to_tf32(v.x * nm);
        p[1] = to_tf32(v.y * nm);
        p[2] = to_tf32(v.z * nm);
        p[3] = to_tf32(v.w * nm);
    }
    // Load W (128x128), cvt to tf32.
#pragma unroll
    for (int it = 0; it < 16; it++) {
        int idx = tid + it * 256;
        int row = idx >> 5;
        int c4  = (idx & 31) << 2;
        float4 v = *(const float4*)&W[row * D + c4];
        float* p = &Ws[row * WS_STRIDE + c4];
        p[0] = to_tf32(v.x);
        p[1] = to_tf32(v.y);
        p[2] = to_tf32(v.z);
        p[3] = to_tf32(v.w);
    }
    __syncthreads();

    int wid = tid >> 5;
    int lane = tid & 31;
    int g = lane >> 2;
    int t = lane & 3;
    int wm = (wid & 3) * 32;   // warp M offset
    int wn = (wid >> 2) * 64;  // warp N offset

    float acc[2][8][4];
#pragma unroll
    for (int mi = 0; mi < 2; mi++)
#pragma unroll
        for (int ni = 0; ni < 8; ni++)
#pragma unroll
            for (int q = 0; q < 4; q++) acc[mi][ni][q] = 0.f;

#pragma unroll
    for (int k0 = 0; k0 < 128; k0 += 8) {
        float a[2][4];
#pragma unroll
        for (int mi = 0; mi < 2; mi++) {
            int r = wm + mi * 16 + g;
            a[mi][0] = As[r * AS_STRIDE + k0 + t];
            a[mi][1] = As[(r + 8) * AS_STRIDE + k0 + t];
            a[mi][2] = As[r * AS_STRIDE + k0 + t + 4];
            a[mi][3] = As[(r + 8) * AS_STRIDE + k0 + t + 4];
        }
        float bb[8][2];
#pragma unroll
        for (int ni = 0; ni < 8; ni++) {
            int c = wn + ni * 8 + g;
            bb[ni][0] = Ws[(k0 + t) * WS_STRIDE + c];
            bb[ni][1] = Ws[(k0 + t + 4) * WS_STRIDE + c];
        }
#pragma unroll
        for (int mi = 0; mi < 2; mi++)
#pragma unroll
            for (int ni = 0; ni < 8; ni++)
                mma_tf32(acc[mi][ni], a[mi], bb[ni]);
    }

    // Epilogue: add bias, store. c0:(g,2t) c1:(g,2t+1) c2:(g+8,2t) c3:(g+8,2t+1)
#pragma unroll
    for (int ni = 0; ni < 8; ni++) {
        int col = wn + ni * 8 + 2 * t;
        float b0 = bias[col];
        float b1 = bias[col + 1];
#pragma unroll
        for (int mi = 0; mi < 2; mi++) {
            int r0 = rowbase + wm + mi * 16 + g;
            if (r0 < N) {
                float2 o = make_float2(acc[mi][ni][0] + b0, acc[mi][ni][1] + b1);
                *(float2*)&outp[r0 * D + col] = o;
            }
            int r1 = r0 + 8;
            if (r1 < N) {
                float2 o = make_float2(acc[mi][ni][2] + b0, acc[mi][ni][3] + b1);
                *(float2*)&outp[r1 * D + col] = o;
            }
        }
    }
}

// ---------------- gather + interleaved e-copy -------------------------------
__device__ __forceinline__ float fast_sigmoid(float x) {
    float t;
    asm("tanh.approx.f32 %0, %1;" : "=f"(t) : "f"(x * 0.5f));
    return fmaf(t, 0.5f, 0.5f);
}

__global__ __launch_bounds__(128)
void k_gather_copy(const float* __restrict__ norm, float* __restrict__ out, int N,
                   int Tg, int NCg,
                   const float4* __restrict__ esrc, float4* __restrict__ edst,
                   long copyBase, long n4total) {
    long b = blockIdx.x;
    long cb  = (b * (long)NCg) / Tg;
    long cb1 = ((b + 1) * (long)NCg) / Tg;
    int tid = threadIdx.x;

    if (cb1 > cb) {
        long base = copyBase + cb * COPY_CHUNK;
#pragma unroll
        for (int it = 0; it < COPY_CHUNK / 128; it++) {
            long idx = base + tid + it * 128;
            if (idx < n4total) __stcs(&edst[idx], __ldcs(&esrc[idx]));
        }
        return;
    }
    int v = (int)(b - cb);
    int d = tid;
    float Ehd = g_Eh[v * D + d];
    int beg = g_off[v];
    int end = g_off[v + 1];
    float num = 0.f, den = 0.f;
    for (int i = beg; i < end; i++) {
        int s = g_csrc[i];
        float Dv = g_Dh[s * D + d];
        float Bv = g_Bh[s * D + d];
        float sg = fast_sigmoid(Dv + Ehd);
        num = fmaf(sg, Bv, num);
        den += sg;
    }
    float nm = norm[v];
    out[v * D + d] = (g_Ah[v * D + d] + __fdividef(num, den + 1e-6f)) * nm;
}

// ---------------- launch -----------------------------------------------------
extern "C" void kernel_launch(void* const* d_in, const int* in_sizes, int n_in,
                              void* d_out, int out_size) {
    const float* h    = (const float*)d_in[0];
    const float* e    = (const float*)d_in[1];
    const float* norm = (const float*)d_in[2];
    const int*   src  = (const int*)d_in[3];
    const int*   dst  = (const int*)d_in[4];
    const float* WA = (const float*)d_in[5];
    const float* bA = (const float*)d_in[6];
    const float* WB = (const float*)d_in[7];
    const float* bB = (const float*)d_in[8];
    const float* WD = (const float*)d_in[9];
    const float* bD = (const float*)d_in[10];
    const float* WE = (const float*)d_in[11];
    const float* bE = (const float*)d_in[12];

    int N = in_sizes[0] / D;
    int E = in_sizes[1] / D;
    float* out = (float*)d_out;

    // e-copy bookkeeping
    long tail = (long)out_size - (long)N * D;
    long n4total = tail > 0 ? tail / 4 : 0;
    const float4* esrc = (const float4*)e;
    float4* edst = (float4*)(out + (size_t)N * D);

    long totalChunks = (n4total + COPY_CHUNK - 1) / COPY_CHUNK;
    int NC1 = (int)(totalChunks < 1024 ? totalChunks : 1024);  // chunks hidden under GEMM
    int NC2 = (int)(totalChunks - NC1);                        // remainder under gather

    // CSR build
    int tb = 256;
    int gN = (N + tb - 1) / tb;
    int gE = (E + tb - 1) / tb;
    k_zero_deg<<<gN, tb>>>(N);
    k_hist<<<gE, tb>>>(dst, E);
    int nb = (N + 255) / 256;
    k_scan1<<<nb, 256>>>(N);
    k_scan2<<<1, 256>>>(nb, N);
    k_scan3<<<gN, tb>>>(N);
    k_scatter<<<gE, tb>>>(src, dst, E);

    // tf32 GEMM (4 matrices) + first slice of e-copy
    int MT = (N + 127) / 128;
    int gemmBlocks = MT * 4;
    int T1 = gemmBlocks + NC1;
    size_t smem = (size_t)(128 * AS_STRIDE + 128 * WS_STRIDE) * sizeof(float);
    cudaFuncSetAttribute(k_gemm4_tf32, cudaFuncAttributeMaxDynamicSharedMemorySize, (int)smem);
    k_gemm4_tf32<<<T1, 256, smem>>>(h, norm, WA, bA, WB, bB, WD, bD, WE, bE,
                                    N, MT, T1, NC1, esrc, edst, n4total);

    // gather + remaining e-copy
    int Tg = N + NC2;
    long copyBase = (long)NC1 * COPY_CHUNK;
    k_gather_copy<<<Tg, 128>>>(norm, out, N, Tg, NC2, esrc, edst, copyBase, n4total);
}

// round 3
// speedup vs baseline: 1.7424x; 1.1979x over previous
#include <cuda_runtime.h>
#include <cuda_bf16.h>
#include <cstdint>

#define D 128
#define MAXN 50176
#define MAXE 800000

// ---------------- scratch ----------------------------------------------------
__device__ float g_Ah[MAXN * D];
__device__ float g_Bh[MAXN * D];
__device__ float g_Dh[MAXN * D];
__device__ float g_Eh[MAXN * D];
__device__ int   g_deg[MAXN];
__device__ int   g_off[MAXN + 1];
__device__ int   g_cur[MAXN];
__device__ int   g_csrc[MAXE];
__device__ int   g_bsums[256];

// ---------------- CSR build --------------------------------------------------
__global__ void k_zero_deg(int N) {
    int i = blockIdx.x * blockDim.x + threadIdx.x;
    if (i < N) g_deg[i] = 0;
}

__global__ void k_hist(const int* __restrict__ dst, int E) {
    int i = blockIdx.x * blockDim.x + threadIdx.x;
    if (i < E) atomicAdd(&g_deg[dst[i]], 1);
}

__global__ void k_scan1(int N) {
    __shared__ int s[256];
    int tid = threadIdx.x;
    int i = blockIdx.x * 256 + tid;
    int v = (i < N) ? g_deg[i] : 0;
    s[tid] = v;
    __syncthreads();
#pragma unroll
    for (int off = 1; off < 256; off <<= 1) {
        int t = (tid >= off) ? s[tid - off] : 0;
        __syncthreads();
        s[tid] += t;
        __syncthreads();
    }
    if (i < N) g_off[i] = s[tid] - v;
    if (tid == 255) g_bsums[blockIdx.x] = s[255];
}

__global__ void k_scan2(int nb, int N) {
    __shared__ int s[256];
    int tid = threadIdx.x;
    int v = (tid < nb) ? g_bsums[tid] : 0;
    s[tid] = v;
    __syncthreads();
#pragma unroll
    for (int off = 1; off < 256; off <<= 1) {
        int t = (tid >= off) ? s[tid - off] : 0;
        __syncthreads();
        s[tid] += t;
        __syncthreads();
    }
    if (tid < nb) g_bsums[tid] = s[tid] - v;
    if (tid == 255) g_off[N] = s[255];
}

__global__ void k_scan3(int N) {
    int i = blockIdx.x * blockDim.x + threadIdx.x;
    if (i < N) {
        int v = g_off[i] + g_bsums[i >> 8];
        g_off[i] = v;
        g_cur[i] = v;
    }
}

__global__ void k_scatter(const int* __restrict__ src, const int* __restrict__ dst, int E) {
    int i = blockIdx.x * blockDim.x + threadIdx.x;
    if (i < E) {
        int d = dst[i];
        int p = atomicAdd(&g_cur[d], 1);
        g_csrc[p] = src[i];
    }
}

// ---------------- tf32 tensor-core 4-way GEMM -------------------------------
#define AS_STRIDE 132
#define WS_STRIDE 136

__device__ __forceinline__ float to_tf32(float x) {
    float r;
    asm("cvt.rna.tf32.f32 %0, %1;" : "=f"(r) : "f"(x));
    return r;
}

__device__ __forceinline__ void mma_tf32(float acc[4], const float a[4], const float b[2]) {
    asm volatile(
        "mma.sync.aligned.m16n8k8.row.col.f32.tf32.tf32.f32 "
        "{%0,%1,%2,%3}, {%4,%5,%6,%7}, {%8,%9}, {%0,%1,%2,%3};\n"
        : "+f"(acc[0]), "+f"(acc[1]), "+f"(acc[2]), "+f"(acc[3])
        : "r"(__float_as_uint(a[0])), "r"(__float_as_uint(a[1])),
          "r"(__float_as_uint(a[2])), "r"(__float_as_uint(a[3])),
          "r"(__float_as_uint(b[0])), "r"(__float_as_uint(b[1])));
}

__global__ __launch_bounds__(256, 1)
void k_gemm4_tf32(const float* __restrict__ h, const float* __restrict__ norm,
                  const float* __restrict__ WA, const float* __restrict__ bA,
                  const float* __restrict__ WB, const float* __restrict__ bB,
                  const float* __restrict__ WD, const float* __restrict__ bD,
                  const float* __restrict__ WE, const float* __restrict__ bE,
                  int N, int MT) {
    int gidx = blockIdx.x;
    int mtile = gidx % MT;
    int which = gidx / MT;
    int tid = threadIdx.x;

    extern __shared__ float sm[];
    float* As = sm;                       // [128][AS_STRIDE]
    float* Ws = sm + 128 * AS_STRIDE;     // [128][WS_STRIDE]

    const float* W; const float* bias; float* outp;
    switch (which) {
        case 0:  W = WA; bias = bA; outp = g_Ah; break;
        case 1:  W = WB; bias = bB; outp = g_Bh; break;
        case 2:  W = WD; bias = bD; outp = g_Dh; break;
        default: W = WE; bias = bE; outp = g_Eh; break;
    }

    int rowbase = mtile * 128;

#pragma unroll
    for (int it = 0; it < 16; it++) {
        int idx = tid + it * 256;
        int row = idx >> 5;
        int c4  = (idx & 31) << 2;
        int gr  = rowbase + row;
        float4 v = make_float4(0.f, 0.f, 0.f, 0.f);
        float nm = 0.f;
        if (gr < N) {
            v = *(const float4*)&h[gr * D + c4];
            nm = norm[gr];
        }
        float* p = &As[row * AS_STRIDE + c4];
        p[0] = to_tf32(v.x * nm);
        p[1] = to_tf32(v.y * nm);
        p[2] = to_tf32(v.z * nm);
        p[3] = to_tf32(v.w * nm);
    }
#pragma unroll
    for (int it = 0; it < 16; it++) {
        int idx = tid + it * 256;
        int row = idx >> 5;
        int c4  = (idx & 31) << 2;
        float4 v = *(const float4*)&W[row * D + c4];
        float* p = &Ws[row * WS_STRIDE + c4];
        p[0] = to_tf32(v.x);
        p[1] = to_tf32(v.y);
        p[2] = to_tf32(v.z);
        p[3] = to_tf32(v.w);
    }
    __syncthreads();

    int wid = tid >> 5;
    int lane = tid & 31;
    int g = lane >> 2;
    int t = lane & 3;
    int wm = (wid & 3) * 32;
    int wn = (wid >> 2) * 64;

    float acc[2][8][4];
#pragma unroll
    for (int mi = 0; mi < 2; mi++)
#pragma unroll
        for (int ni = 0; ni < 8; ni++)
#pragma unroll
            for (int q = 0; q < 4; q++) acc[mi][ni][q] = 0.f;

#pragma unroll
    for (int k0 = 0; k0 < 128; k0 += 8) {
        float a[2][4];
#pragma unroll
        for (int mi = 0; mi < 2; mi++) {
            int r = wm + mi * 16 + g;
            a[mi][0] = As[r * AS_STRIDE + k0 + t];
            a[mi][1] = As[(r + 8) * AS_STRIDE + k0 + t];
            a[mi][2] = As[r * AS_STRIDE + k0 + t + 4];
            a[mi][3] = As[(r + 8) * AS_STRIDE + k0 + t + 4];
        }
        float bb[8][2];
#pragma unroll
        for (int ni = 0; ni < 8; ni++) {
            int c = wn + ni * 8 + g;
            bb[ni][0] = Ws[(k0 + t) * WS_STRIDE + c];
            bb[ni][1] = Ws[(k0 + t + 4) * WS_STRIDE + c];
        }
#pragma unroll
        for (int mi = 0; mi < 2; mi++)
#pragma unroll
            for (int ni = 0; ni < 8; ni++)
                mma_tf32(acc[mi][ni], a[mi], bb[ni]);
    }

#pragma unroll
    for (int ni = 0; ni < 8; ni++) {
        int col = wn + ni * 8 + 2 * t;
        float b0 = bias[col];
        float b1 = bias[col + 1];
#pragma unroll
        for (int mi = 0; mi < 2; mi++) {
            int r0 = rowbase + wm + mi * 16 + g;
            if (r0 < N) {
                float2 o = make_float2(acc[mi][ni][0] + b0, acc[mi][ni][1] + b1);
                *(float2*)&outp[r0 * D + col] = o;
            }
            int r1 = r0 + 8;
            if (r1 < N) {
                float2 o = make_float2(acc[mi][ni][2] + b0, acc[mi][ni][3] + b1);
                *(float2*)&outp[r1 * D + col] = o;
            }
        }
    }
}

// ---------------- gather (float2 lanes, csrc prefetch) -----------------------
__device__ __forceinline__ float fast_sigmoid(float x) {
    float t;
    asm("tanh.approx.f32 %0, %1;" : "=f"(t) : "f"(x * 0.5f));
    return fmaf(t, 0.5f, 0.5f);
}

__global__ __launch_bounds__(256)
void k_gather(const float* __restrict__ norm, float* __restrict__ out, int N) {
    int tid = threadIdx.x;
    int v = blockIdx.x * 4 + (tid >> 6);
    if (v >= N) return;
    int d2 = tid & 63;

    const float2* Eh2 = (const float2*)g_Eh;
    const float2* Dh2 = (const float2*)g_Dh;
    const float2* Bh2 = (const float2*)g_Bh;
    const float2* Ah2 = (const float2*)g_Ah;

    float2 eh = Eh2[v * 64 + d2];
    int beg = g_off[v];
    int end = g_off[v + 1];
    float2 num = make_float2(0.f, 0.f);
    float2 den = make_float2(0.f, 0.f);

    int sn = (beg < end) ? g_csrc[beg] : 0;
    for (int i = beg; i < end; i++) {
        int s = sn;
        if (i + 1 < end) sn = g_csrc[i + 1];
        float2 Dv = Dh2[s * 64 + d2];
        float2 Bv = Bh2[s * 64 + d2];
        float sg0 = fast_sigmoid(Dv.x + eh.x);
        float sg1 = fast_sigmoid(Dv.y + eh.y);
        num.x = fmaf(sg0, Bv.x, num.x);
        num.y = fmaf(sg1, Bv.y, num.y);
        den.x += sg0;
        den.y += sg1;
    }
    float nm = norm[v];
    float2 Av = Ah2[v * 64 + d2];
    float2 o;
    o.x = (Av.x + __fdividef(num.x, den.x + 1e-6f)) * nm;
    o.y = (Av.y + __fdividef(num.y, den.y + 1e-6f)) * nm;
    ((float2*)out)[v * 64 + d2] = o;
}

// ---------------- e passthrough copy (streaming) -----------------------------
__global__ __launch_bounds__(256)
void k_copy(const float4* __restrict__ s, float4* __restrict__ dt, long n4) {
    long i = blockIdx.x * 256L + threadIdx.x;
    long stride = (long)gridDim.x * 256L;
    for (; i < n4; i += stride) {
        __stcs(&dt[i], __ldcs(&s[i]));
    }
}

// ---------------- launch -----------------------------------------------------
extern "C" void kernel_launch(void* const* d_in, const int* in_sizes, int n_in,
                              void* d_out, int out_size) {
    const float* h    = (const float*)d_in[0];
    const float* e    = (const float*)d_in[1];
    const float* norm = (const float*)d_in[2];
    const int*   src  = (const int*)d_in[3];
    const int*   dst  = (const int*)d_in[4];
    const float* WA = (const float*)d_in[5];
    const float* bA = (const float*)d_in[6];
    const float* WB = (const float*)d_in[7];
    const float* bB = (const float*)d_in[8];
    const float* WD = (const float*)d_in[9];
    const float* bD = (const float*)d_in[10];
    const float* WE = (const float*)d_in[11];
    const float* bE = (const float*)d_in[12];

    int N = in_sizes[0] / D;
    int E = in_sizes[1] / D;
    float* out = (float*)d_out;

    long tail = (long)out_size - (long)N * D;
    long n4total = tail > 0 ? tail / 4 : 0;
    const float4* esrc = (const float4*)e;
    float4* edst = (float4*)(out + (size_t)N * D);

    // one-time stream/event setup (host resources only; no device allocation)
    static cudaStream_t s1 = nullptr, s2 = nullptr;
    static cudaEvent_t evRoot = nullptr, evCsr = nullptr, evCopy = nullptr;
    if (s1 == nullptr) {
        cudaStreamCreateWithFlags(&s1, cudaStreamNonBlocking);
        cudaStreamCreateWithFlags(&s2, cudaStreamNonBlocking);
        cudaEventCreateWithFlags(&evRoot, cudaEventDisableTiming);
        cudaEventCreateWithFlags(&evCsr,  cudaEventDisableTiming);
        cudaEventCreateWithFlags(&evCopy, cudaEventDisableTiming);
    }

    int tb = 256;
    int gN = (N + tb - 1) / tb;
    int gE = (E + tb - 1) / tb;
    int nb = (N + 255) / 256;

    // fork
    cudaEventRecord(evRoot, 0);
    cudaStreamWaitEvent(s1, evRoot, 0);
    cudaStreamWaitEvent(s2, evRoot, 0);

    // branch s1: CSR build
    k_zero_deg<<<gN, tb, 0, s1>>>(N);
    k_hist<<<gE, tb, 0, s1>>>(dst, E);
    k_scan1<<<nb, 256, 0, s1>>>(N);
    k_scan2<<<1, 256, 0, s1>>>(nb, N);
    k_scan3<<<gN, tb, 0, s1>>>(N);
    k_scatter<<<gE, tb, 0, s1>>>(src, dst, E);
    cudaEventRecord(evCsr, s1);

    // branch s2: e passthrough copy (runs concurrently with GEMM + gather)
    if (n4total > 0) {
        k_copy<<<2048, 256, 0, s2>>>(esrc, edst, n4total);
    }
    cudaEventRecord(evCopy, s2);

    // main branch: GEMM
    int MT = (N + 127) / 128;
    size_t smem = (size_t)(128 * AS_STRIDE + 128 * WS_STRIDE) * sizeof(float);
    cudaFuncSetAttribute(k_gemm4_tf32, cudaFuncAttributeMaxDynamicSharedMemorySize, (int)smem);
    k_gemm4_tf32<<<MT * 4, 256, smem>>>(h, norm, WA, bA, WB, bB, WD, bD, WE, bE, N, MT);

    // join CSR, then gather
    cudaStreamWaitEvent(0, evCsr, 0);
    k_gather<<<(N + 3) / 4, 256>>>(norm, out, N);

    // join copy
    cudaStreamWaitEvent(0, evCopy, 0);
}